// round 1
// baseline (speedup 1.0000x reference)
#include <cuda_runtime.h>
#include <math.h>

#define B_ 64
#define S_ 4096
#define H_ 512
#define A_ 256
#define IN_ 256
#define NCHUNK 16
#define CHUNK (S_ / NCHUNK)            // 256 rows per block
#define WARPS_B 8
#define ROWS_PER_WARP (CHUNK / WARPS_B) // 32

// Scratch (no allocations allowed) ------------------------------------------
__device__ float g_qt[B_ * H_];            // folded query  q~ = (Q @ Wk^T)
__device__ float g_cst[B_];                // Q . bk
__device__ float g_pm[B_ * NCHUNK];        // per-chunk running max
__device__ float g_pl[B_ * NCHUNK];        // per-chunk exp-sum
__device__ float g_pc[B_ * NCHUNK * H_];   // per-chunk weighted hidden sum (2 MB)

// ---------------------------------------------------------------------------
// Kernel A: Q = x@Wq + bq ; q~ = Q @ Wk^T ; const_b = Q . bk
// grid = B_, block = 512
__global__ __launch_bounds__(512) void qproj_kernel(
    const float* __restrict__ x, const float* __restrict__ Wq,
    const float* __restrict__ bq, const float* __restrict__ Wk,
    const float* __restrict__ bk)
{
    const int b = blockIdx.x;
    const int tid = threadIdx.x;
    __shared__ float shQ[A_];
    __shared__ float shP[A_];

    if (tid < A_) {
        float acc = bq[tid];
        const float* xr = x + b * IN_;
        #pragma unroll 8
        for (int i = 0; i < IN_; ++i)
            acc = fmaf(xr[i], Wq[i * A_ + tid], acc);  // column read: coalesced
        shQ[tid] = acc;
        shP[tid] = acc * bk[tid];
    }
    __syncthreads();

    // one thread per hidden dim h (512 threads == H_)
    {
        const int h = tid;
        float acc = 0.f;
        const float* wr = Wk + h * A_;
        #pragma unroll 8
        for (int a = 0; a < A_; ++a)
            acc = fmaf(shQ[a], wr[a], acc);
        g_qt[b * H_ + h] = acc;
    }
    if (tid == 0) {
        float s = 0.f;
        for (int a = 0; a < A_; ++a) s += shP[a];
        g_cst[b] = s;
    }
}

// ---------------------------------------------------------------------------
// Kernel B: streaming online-softmax pass over history_h.
// grid = (NCHUNK, B_), block = 256 (8 warps, 32 rows each)
// Per-lane data layout over the 512-dim hidden vector:
//   element index = j*128 + lane*4 + k   (j in 0..3, k in 0..3)  -> float4 loads
__global__ __launch_bounds__(256) void attn_pass_kernel(const float* __restrict__ hist)
{
    const int b     = blockIdx.y;
    const int chunk = blockIdx.x;
    const int tid   = threadIdx.x;
    const int w     = tid >> 5;
    const int lane  = tid & 31;

    // load folded query into registers (same for every warp)
    float4 q4[4];
    const float4* qv = (const float4*)(g_qt + b * H_);
    #pragma unroll
    for (int j = 0; j < 4; ++j) q4[j] = qv[j * 32 + lane];

    const float cb = g_cst[b];
    const float inv_scale = 0.0625f; // 1/sqrt(256)

    float m = -INFINITY, l = 0.f;
    float4 acc[4];
    #pragma unroll
    for (int j = 0; j < 4; ++j) acc[j] = make_float4(0.f, 0.f, 0.f, 0.f);

    const int s0 = chunk * CHUNK + w * ROWS_PER_WARP;
    for (int r = 0; r < ROWS_PER_WARP; ++r) {
        const size_t row = ((size_t)b * S_ + (size_t)(s0 + r)) * H_;
        const float4* hv = (const float4*)(hist + row);
        float4 h4[4];
        #pragma unroll
        for (int j = 0; j < 4; ++j) h4[j] = hv[j * 32 + lane];  // 4x LDG.128, MLP=4

        float dot = 0.f;
        #pragma unroll
        for (int j = 0; j < 4; ++j) {
            dot = fmaf(h4[j].x, q4[j].x, dot);
            dot = fmaf(h4[j].y, q4[j].y, dot);
            dot = fmaf(h4[j].z, q4[j].z, dot);
            dot = fmaf(h4[j].w, q4[j].w, dot);
        }
        #pragma unroll
        for (int o = 16; o > 0; o >>= 1)
            dot += __shfl_xor_sync(0xffffffffu, dot, o);  // butterfly: all lanes get sum

        const float score = (dot + cb) * inv_scale;

        if (score > m) {                       // uniform across warp (no divergence)
            const float rsc = __expf(m - score);
            l *= rsc;
            #pragma unroll
            for (int j = 0; j < 4; ++j) {
                acc[j].x *= rsc; acc[j].y *= rsc; acc[j].z *= rsc; acc[j].w *= rsc;
            }
            m = score;
        }
        const float wgt = __expf(score - m);
        l += wgt;
        #pragma unroll
        for (int j = 0; j < 4; ++j) {
            acc[j].x = fmaf(wgt, h4[j].x, acc[j].x);
            acc[j].y = fmaf(wgt, h4[j].y, acc[j].y);
            acc[j].z = fmaf(wgt, h4[j].z, acc[j].z);
            acc[j].w = fmaf(wgt, h4[j].w, acc[j].w);
        }
    }

    // ---- deterministic block combine (no float atomics) ----
    __shared__ float s_m[WARPS_B], s_l[WARPS_B], s_scale[WARPS_B];
    __shared__ float s_c[WARPS_B][H_];   // 16 KB
    if (lane == 0) { s_m[w] = m; s_l[w] = l; }
    __syncthreads();
    if (tid == 0) {
        float mb = s_m[0];
        #pragma unroll
        for (int i = 1; i < WARPS_B; ++i) mb = fmaxf(mb, s_m[i]);
        float lb = 0.f;
        #pragma unroll
        for (int i = 0; i < WARPS_B; ++i) {
            const float sc_ = __expf(s_m[i] - mb);
            s_scale[i] = sc_;
            lb = fmaf(sc_, s_l[i], lb);
        }
        const int idx = b * NCHUNK + chunk;
        g_pm[idx] = mb;
        g_pl[idx] = lb;
    }
    __syncthreads();

    const float sc_w = s_scale[w];
    #pragma unroll
    for (int j = 0; j < 4; ++j) {
        float4 v = acc[j];
        v.x *= sc_w; v.y *= sc_w; v.z *= sc_w; v.w *= sc_w;
        ((float4*)&s_c[w][j * 128])[lane] = v;   // STS.128, conflict-free
    }
    __syncthreads();

    float* gout = g_pc + (size_t)(b * NCHUNK + chunk) * H_;
    for (int hh = tid; hh < H_; hh += 256) {
        float t = 0.f;
        #pragma unroll
        for (int wi = 0; wi < WARPS_B; ++wi) t += s_c[wi][hh];
        gout[hh] = t;
    }
}

// ---------------------------------------------------------------------------
// Kernel C: combine chunk partials per batch, then context = (c~/l) @ Wv + bv
// grid = B_, block = 256 (one thread per output attn dim)
__global__ __launch_bounds__(256) void finalize_kernel(
    const float* __restrict__ Wv, const float* __restrict__ bv,
    float* __restrict__ out)
{
    const int b = blockIdx.x;
    const int tid = threadIdx.x;
    __shared__ float s_scale[NCHUNK];
    __shared__ float s_c[H_];
    __shared__ float s_invl;

    if (tid == 0) {
        float mg = g_pm[b * NCHUNK];
        #pragma unroll
        for (int c = 1; c < NCHUNK; ++c) mg = fmaxf(mg, g_pm[b * NCHUNK + c]);
        float lg = 0.f;
        #pragma unroll
        for (int c = 0; c < NCHUNK; ++c) {
            const float sc_ = __expf(g_pm[b * NCHUNK + c] - mg);
            s_scale[c] = sc_;
            lg = fmaf(sc_, g_pl[b * NCHUNK + c], lg);
        }
        s_invl = 1.0f / lg;
    }
    __syncthreads();

    for (int hh = tid; hh < H_; hh += 256) {
        float t = 0.f;
        #pragma unroll
        for (int c = 0; c < NCHUNK; ++c)
            t = fmaf(s_scale[c], g_pc[(size_t)(b * NCHUNK + c) * H_ + hh], t);
        s_c[hh] = t * s_invl;
    }
    __syncthreads();

    const int a = tid;
    float accum = bv[a];
    #pragma unroll 8
    for (int hh = 0; hh < H_; ++hh)
        accum = fmaf(s_c[hh], Wv[hh * A_ + a], accum);  // coalesced Wv column read
    out[b * A_ + a] = accum;
}

// ---------------------------------------------------------------------------
extern "C" void kernel_launch(void* const* d_in, const int* in_sizes, int n_in,
                              void* d_out, int out_size)
{
    const float* x    = (const float*)d_in[0];
    const float* hist = (const float*)d_in[1];
    const float* Wq   = (const float*)d_in[2];
    const float* bq   = (const float*)d_in[3];
    const float* Wk   = (const float*)d_in[4];
    const float* bk   = (const float*)d_in[5];
    const float* Wv   = (const float*)d_in[6];
    const float* bv   = (const float*)d_in[7];
    float* out = (float*)d_out;

    qproj_kernel<<<B_, 512>>>(x, Wq, bq, Wk, bk);
    attn_pass_kernel<<<dim3(NCHUNK, B_), 256>>>(hist);
    finalize_kernel<<<B_, 256>>>(Wv, bv, out);
}

// round 2
// speedup vs baseline: 1.3770x; 1.3770x over previous
#include <cuda_runtime.h>
#include <math.h>

#define B_ 64
#define S_ 4096
#define H_ 512
#define A_ 256
#define IN_ 256
#define NCHUNK 16
#define CHUNK (S_ / NCHUNK)            // 256 rows per block
#define WARPS_B 8
#define ROWS_PER_WARP (CHUNK / WARPS_B) // 32

// Scratch (no allocations allowed) ------------------------------------------
__device__ float g_Q[B_ * A_];             // Q = x@Wq + bq
__device__ float g_qt[B_ * H_];            // folded query  q~ = Q @ Wk^T
__device__ float g_cst[B_];                // Q . bk
__device__ float g_pm[B_ * NCHUNK];        // per-chunk running max
__device__ float g_pl[B_ * NCHUNK];        // per-chunk exp-sum
__device__ float g_pc[B_ * NCHUNK * H_];   // per-chunk weighted hidden sum (2 MB)

// ---------------------------------------------------------------------------
// Kernel A1: Q = x@Wq + bq  and  cst[b] = Q[b] . bk
// grid = B_, block = 256 (one thread per attn dim; coalesced Wq column reads)
__global__ __launch_bounds__(256) void q_kernel(
    const float* __restrict__ x, const float* __restrict__ Wq,
    const float* __restrict__ bq, const float* __restrict__ bk)
{
    const int b = blockIdx.x;
    const int a = threadIdx.x;
    __shared__ float shP[A_];

    const float* xr = x + b * IN_;
    float a0 = 0.f, a1 = 0.f, a2 = 0.f, a3 = 0.f;
    #pragma unroll 4
    for (int i = 0; i < IN_; i += 4) {
        a0 = fmaf(xr[i + 0], Wq[(i + 0) * A_ + a], a0);
        a1 = fmaf(xr[i + 1], Wq[(i + 1) * A_ + a], a1);
        a2 = fmaf(xr[i + 2], Wq[(i + 2) * A_ + a], a2);
        a3 = fmaf(xr[i + 3], Wq[(i + 3) * A_ + a], a3);
    }
    const float q = (a0 + a1) + (a2 + a3) + bq[a];
    g_Q[b * A_ + a] = q;
    shP[a] = q * bk[a];
    __syncthreads();

    // tree reduce shP -> cst[b]
    for (int s = 128; s > 0; s >>= 1) {
        if (a < s) shP[a] += shP[a + s];
        __syncthreads();
    }
    if (a == 0) g_cst[b] = shP[0];
}

// ---------------------------------------------------------------------------
// Kernel A2: q~[b,h] = sum_a Q[b,a] * Wk[h,a]  — one WARP per output element.
// grid = B_*H_/8 = 4096 blocks, block = 256 (8 warps). Fully coalesced Wk reads.
__global__ __launch_bounds__(256) void qt_kernel(const float* __restrict__ Wk)
{
    const int gw   = blockIdx.x * WARPS_B + (threadIdx.x >> 5); // global warp id
    const int lane = threadIdx.x & 31;
    const int b = gw >> 9;          // /512
    const int h = gw & (H_ - 1);    // %512

    const float* wr = Wk + h * A_;
    const float* qr = g_Q + b * A_;
    float acc = 0.f;
    #pragma unroll
    for (int j = 0; j < A_ / 32; ++j) {
        const int a = j * 32 + lane;             // coalesced across lanes
        acc = fmaf(qr[a], wr[a], acc);
    }
    #pragma unroll
    for (int o = 16; o > 0; o >>= 1)
        acc += __shfl_xor_sync(0xffffffffu, acc, o);
    if (lane == 0) g_qt[b * H_ + h] = acc;
}

// ---------------------------------------------------------------------------
// Kernel B: streaming online-softmax pass over history_h.
// grid = (NCHUNK, B_), block = 256 (8 warps, 32 rows each)
// Per-lane layout of the 512-dim hidden vector: float4 index j*32+lane (j<4).
// Software-pipelined: next row's 4x LDG.128 issued before current row compute
// -> 8 outstanding LDG.128 per warp (MLP doubled).
__global__ __launch_bounds__(256) void attn_pass_kernel(const float* __restrict__ hist)
{
    const int b     = blockIdx.y;
    const int chunk = blockIdx.x;
    const int tid   = threadIdx.x;
    const int w     = tid >> 5;
    const int lane  = tid & 31;

    float4 q4[4];
    const float4* qv = (const float4*)(g_qt + b * H_);
    #pragma unroll
    for (int j = 0; j < 4; ++j) q4[j] = qv[j * 32 + lane];

    const float cb = g_cst[b];
    const float inv_scale = 0.0625f; // 1/sqrt(256)

    float m = -INFINITY, l = 0.f;
    float4 acc[4];
    #pragma unroll
    for (int j = 0; j < 4; ++j) acc[j] = make_float4(0.f, 0.f, 0.f, 0.f);

    const int s0 = chunk * CHUNK + w * ROWS_PER_WARP;
    const float4* rowp = (const float4*)(hist + ((size_t)b * S_ + s0) * H_);
    const int row_stride4 = H_ / 4;   // float4s per row

    float4 h4[4], n4[4];
    #pragma unroll
    for (int j = 0; j < 4; ++j) h4[j] = rowp[j * 32 + lane];   // prologue load

    for (int r = 0; r < ROWS_PER_WARP; ++r) {
        if (r < ROWS_PER_WARP - 1) {
            const float4* np = rowp + (size_t)(r + 1) * row_stride4;
            #pragma unroll
            for (int j = 0; j < 4; ++j) n4[j] = np[j * 32 + lane];  // prefetch
        }

        float dot = 0.f;
        #pragma unroll
        for (int j = 0; j < 4; ++j) {
            dot = fmaf(h4[j].x, q4[j].x, dot);
            dot = fmaf(h4[j].y, q4[j].y, dot);
            dot = fmaf(h4[j].z, q4[j].z, dot);
            dot = fmaf(h4[j].w, q4[j].w, dot);
        }
        #pragma unroll
        for (int o = 16; o > 0; o >>= 1)
            dot += __shfl_xor_sync(0xffffffffu, dot, o);

        const float score = (dot + cb) * inv_scale;

        if (score > m) {                     // warp-uniform
            const float rsc = __expf(m - score);
            l *= rsc;
            #pragma unroll
            for (int j = 0; j < 4; ++j) {
                acc[j].x *= rsc; acc[j].y *= rsc; acc[j].z *= rsc; acc[j].w *= rsc;
            }
            m = score;
        }
        const float wgt = __expf(score - m);
        l += wgt;
        #pragma unroll
        for (int j = 0; j < 4; ++j) {
            acc[j].x = fmaf(wgt, h4[j].x, acc[j].x);
            acc[j].y = fmaf(wgt, h4[j].y, acc[j].y);
            acc[j].z = fmaf(wgt, h4[j].z, acc[j].z);
            acc[j].w = fmaf(wgt, h4[j].w, acc[j].w);
        }

        #pragma unroll
        for (int j = 0; j < 4; ++j) h4[j] = n4[j];
    }

    // ---- deterministic block combine (no float atomics) ----
    __shared__ float s_m[WARPS_B], s_l[WARPS_B], s_scale[WARPS_B];
    __shared__ float s_c[WARPS_B][H_];   // 16 KB
    if (lane == 0) { s_m[w] = m; s_l[w] = l; }
    __syncthreads();
    if (tid == 0) {
        float mb = s_m[0];
        #pragma unroll
        for (int i = 1; i < WARPS_B; ++i) mb = fmaxf(mb, s_m[i]);
        float lb = 0.f;
        #pragma unroll
        for (int i = 0; i < WARPS_B; ++i) {
            const float sc_ = __expf(s_m[i] - mb);
            s_scale[i] = sc_;
            lb = fmaf(sc_, s_l[i], lb);
        }
        const int idx = b * NCHUNK + chunk;
        g_pm[idx] = mb;
        g_pl[idx] = lb;
    }
    __syncthreads();

    const float sc_w = s_scale[w];
    #pragma unroll
    for (int j = 0; j < 4; ++j) {
        float4 v = acc[j];
        v.x *= sc_w; v.y *= sc_w; v.z *= sc_w; v.w *= sc_w;
        ((float4*)&s_c[w][j * 128])[lane] = v;   // STS.128, conflict-free
    }
    __syncthreads();

    float* gout = g_pc + (size_t)(b * NCHUNK + chunk) * H_;
    for (int hh = tid; hh < H_; hh += 256) {
        float t = 0.f;
        #pragma unroll
        for (int wi = 0; wi < WARPS_B; ++wi) t += s_c[wi][hh];
        gout[hh] = t;
    }
}

// ---------------------------------------------------------------------------
// Kernel C: combine chunk partials per batch, then context = (c~/l) @ Wv + bv
// grid = B_, block = 256 (one thread per output attn dim)
__global__ __launch_bounds__(256) void finalize_kernel(
    const float* __restrict__ Wv, const float* __restrict__ bv,
    float* __restrict__ out)
{
    const int b = blockIdx.x;
    const int tid = threadIdx.x;
    __shared__ float s_scale[NCHUNK];
    __shared__ float s_c[H_];
    __shared__ float s_invl;

    if (tid == 0) {
        float mg = g_pm[b * NCHUNK];
        #pragma unroll
        for (int c = 1; c < NCHUNK; ++c) mg = fmaxf(mg, g_pm[b * NCHUNK + c]);
        float lg = 0.f;
        #pragma unroll
        for (int c = 0; c < NCHUNK; ++c) {
            const float sc_ = __expf(g_pm[b * NCHUNK + c] - mg);
            s_scale[c] = sc_;
            lg = fmaf(sc_, g_pl[b * NCHUNK + c], lg);
        }
        s_invl = 1.0f / lg;
    }
    __syncthreads();

    for (int hh = tid; hh < H_; hh += 256) {
        float t = 0.f;
        #pragma unroll
        for (int c = 0; c < NCHUNK; ++c)
            t = fmaf(s_scale[c], g_pc[(size_t)(b * NCHUNK + c) * H_ + hh], t);
        s_c[hh] = t * s_invl;
    }
    __syncthreads();

    const int a = tid;
    float accum = bv[a];
    #pragma unroll 8
    for (int hh = 0; hh < H_; ++hh)
        accum = fmaf(s_c[hh], Wv[hh * A_ + a], accum);  // coalesced Wv column read
    out[b * A_ + a] = accum;
}

// ---------------------------------------------------------------------------
extern "C" void kernel_launch(void* const* d_in, const int* in_sizes, int n_in,
                              void* d_out, int out_size)
{
    const float* x    = (const float*)d_in[0];
    const float* hist = (const float*)d_in[1];
    const float* Wq   = (const float*)d_in[2];
    const float* bq   = (const float*)d_in[3];
    const float* Wk   = (const float*)d_in[4];
    const float* bk   = (const float*)d_in[5];
    const float* Wv   = (const float*)d_in[6];
    const float* bv   = (const float*)d_in[7];
    float* out = (float*)d_out;

    q_kernel<<<B_, 256>>>(x, Wq, bq, bk);
    qt_kernel<<<(B_ * H_) / WARPS_B, 256>>>(Wk);
    attn_pass_kernel<<<dim3(NCHUNK, B_), 256>>>(hist);
    finalize_kernel<<<B_, 256>>>(Wv, bv, out);
}

// round 3
// speedup vs baseline: 1.6162x; 1.1737x over previous
#include <cuda_runtime.h>
#include <math.h>

#define B_ 64
#define S_ 4096
#define H_ 512
#define A_ 256
#define IN_ 256
#define NCHUNK 16
#define CHUNK (S_ / NCHUNK)            // 256 rows per block
#define WARPS_B 8
#define ROWS_PER_WARP (CHUNK / WARPS_B) // 32

// Scratch (no allocations allowed) ------------------------------------------
__device__ float g_Q[B_ * A_];             // Q = x@Wq + bq
__device__ float g_qt[B_ * H_];            // folded query  q~ = Q @ Wk^T
__device__ float g_cst[B_];                // Q . bk
__device__ float g_pm[B_ * NCHUNK];        // per-chunk running max
__device__ float g_pl[B_ * NCHUNK];        // per-chunk exp-sum
__device__ float g_pc[B_ * NCHUNK * H_];   // per-chunk weighted hidden sum (2 MB)
__device__ float g_ctx[B_ * H_];           // normalized context (pre-Wv)
__device__ float g_WvT[A_ * H_];           // transposed Wv (A-major)

// ---------------------------------------------------------------------------
// Kernel A1: Q = x@Wq + bq  and  cst[b] = Q[b] . bk
__global__ __launch_bounds__(256) void q_kernel(
    const float* __restrict__ x, const float* __restrict__ Wq,
    const float* __restrict__ bq, const float* __restrict__ bk)
{
    const int b = blockIdx.x;
    const int a = threadIdx.x;
    __shared__ float shP[A_];

    const float* xr = x + b * IN_;
    float a0 = 0.f, a1 = 0.f, a2 = 0.f, a3 = 0.f;
    #pragma unroll 4
    for (int i = 0; i < IN_; i += 4) {
        a0 = fmaf(xr[i + 0], Wq[(i + 0) * A_ + a], a0);
        a1 = fmaf(xr[i + 1], Wq[(i + 1) * A_ + a], a1);
        a2 = fmaf(xr[i + 2], Wq[(i + 2) * A_ + a], a2);
        a3 = fmaf(xr[i + 3], Wq[(i + 3) * A_ + a], a3);
    }
    const float q = (a0 + a1) + (a2 + a3) + bq[a];
    g_Q[b * A_ + a] = q;
    shP[a] = q * bk[a];
    __syncthreads();

    for (int s = 128; s > 0; s >>= 1) {
        if (a < s) shP[a] += shP[a + s];
        __syncthreads();
    }
    if (a == 0) g_cst[b] = shP[0];
}

// ---------------------------------------------------------------------------
// Kernel A2: q~[b,h] = sum_a Q[b,a] * Wk[h,a]  — one WARP per output element.
__global__ __launch_bounds__(256) void qt_kernel(const float* __restrict__ Wk)
{
    const int gw   = blockIdx.x * WARPS_B + (threadIdx.x >> 5);
    const int lane = threadIdx.x & 31;
    const int b = gw >> 9;          // /512
    const int h = gw & (H_ - 1);    // %512

    const float* wr = Wk + h * A_;
    const float* qr = g_Q + b * A_;
    float acc = 0.f;
    #pragma unroll
    for (int j = 0; j < A_ / 32; ++j) {
        const int a = j * 32 + lane;
        acc = fmaf(qr[a], wr[a], acc);
    }
    #pragma unroll
    for (int o = 16; o > 0; o >>= 1)
        acc += __shfl_xor_sync(0xffffffffu, acc, o);
    if (lane == 0) g_qt[b * H_ + h] = acc;
}

// ---------------------------------------------------------------------------
// Kernel A3: Wv transpose -> g_WvT[a][h]  (tiled, padded shared)
// grid = (A_/32, H_/32) = (8,16), block = (32, 8)
__global__ __launch_bounds__(256) void wvT_kernel(const float* __restrict__ Wv)
{
    __shared__ float tile[32][33];
    const int a0 = blockIdx.x * 32;
    const int h0 = blockIdx.y * 32;
    const int tx = threadIdx.x;      // 0..31
    const int ty = threadIdx.y;      // 0..7

    #pragma unroll
    for (int i = 0; i < 4; ++i) {
        const int h = h0 + ty + i * 8;
        tile[ty + i * 8][tx] = Wv[h * A_ + a0 + tx];   // coalesced read
    }
    __syncthreads();
    #pragma unroll
    for (int i = 0; i < 4; ++i) {
        const int a = a0 + ty + i * 8;
        g_WvT[a * H_ + h0 + tx] = tile[tx][ty + i * 8]; // coalesced write
    }
}

// ---------------------------------------------------------------------------
// Kernel B: streaming online-softmax pass over history_h.
// grid = (NCHUNK, B_), block = 256 (8 warps, 32 rows each), pipelined loads.
__global__ __launch_bounds__(256) void attn_pass_kernel(const float* __restrict__ hist)
{
    const int b     = blockIdx.y;
    const int chunk = blockIdx.x;
    const int tid   = threadIdx.x;
    const int w     = tid >> 5;
    const int lane  = tid & 31;

    float4 q4[4];
    const float4* qv = (const float4*)(g_qt + b * H_);
    #pragma unroll
    for (int j = 0; j < 4; ++j) q4[j] = qv[j * 32 + lane];

    const float cb = g_cst[b];
    const float inv_scale = 0.0625f; // 1/sqrt(256)

    float m = -INFINITY, l = 0.f;
    float4 acc[4];
    #pragma unroll
    for (int j = 0; j < 4; ++j) acc[j] = make_float4(0.f, 0.f, 0.f, 0.f);

    const int s0 = chunk * CHUNK + w * ROWS_PER_WARP;
    const float4* rowp = (const float4*)(hist + ((size_t)b * S_ + s0) * H_);
    const int row_stride4 = H_ / 4;

    float4 h4[4], n4[4];
    #pragma unroll
    for (int j = 0; j < 4; ++j) h4[j] = rowp[j * 32 + lane];

    for (int r = 0; r < ROWS_PER_WARP; ++r) {
        if (r < ROWS_PER_WARP - 1) {
            const float4* np = rowp + (size_t)(r + 1) * row_stride4;
            #pragma unroll
            for (int j = 0; j < 4; ++j) n4[j] = np[j * 32 + lane];
        }

        float dot = 0.f;
        #pragma unroll
        for (int j = 0; j < 4; ++j) {
            dot = fmaf(h4[j].x, q4[j].x, dot);
            dot = fmaf(h4[j].y, q4[j].y, dot);
            dot = fmaf(h4[j].z, q4[j].z, dot);
            dot = fmaf(h4[j].w, q4[j].w, dot);
        }
        #pragma unroll
        for (int o = 16; o > 0; o >>= 1)
            dot += __shfl_xor_sync(0xffffffffu, dot, o);

        const float score = (dot + cb) * inv_scale;

        if (score > m) {                     // warp-uniform
            const float rsc = __expf(m - score);
            l *= rsc;
            #pragma unroll
            for (int j = 0; j < 4; ++j) {
                acc[j].x *= rsc; acc[j].y *= rsc; acc[j].z *= rsc; acc[j].w *= rsc;
            }
            m = score;
        }
        const float wgt = __expf(score - m);
        l += wgt;
        #pragma unroll
        for (int j = 0; j < 4; ++j) {
            acc[j].x = fmaf(wgt, h4[j].x, acc[j].x);
            acc[j].y = fmaf(wgt, h4[j].y, acc[j].y);
            acc[j].z = fmaf(wgt, h4[j].z, acc[j].z);
            acc[j].w = fmaf(wgt, h4[j].w, acc[j].w);
        }

        #pragma unroll
        for (int j = 0; j < 4; ++j) h4[j] = n4[j];
    }

    // ---- deterministic block combine ----
    __shared__ float s_m[WARPS_B], s_l[WARPS_B], s_scale[WARPS_B];
    __shared__ float s_c[WARPS_B][H_];
    if (lane == 0) { s_m[w] = m; s_l[w] = l; }
    __syncthreads();
    if (tid == 0) {
        float mb = s_m[0];
        #pragma unroll
        for (int i = 1; i < WARPS_B; ++i) mb = fmaxf(mb, s_m[i]);
        float lb = 0.f;
        #pragma unroll
        for (int i = 0; i < WARPS_B; ++i) {
            const float sc_ = __expf(s_m[i] - mb);
            s_scale[i] = sc_;
            lb = fmaf(sc_, s_l[i], lb);
        }
        const int idx = b * NCHUNK + chunk;
        g_pm[idx] = mb;
        g_pl[idx] = lb;
    }
    __syncthreads();

    const float sc_w = s_scale[w];
    #pragma unroll
    for (int j = 0; j < 4; ++j) {
        float4 v = acc[j];
        v.x *= sc_w; v.y *= sc_w; v.z *= sc_w; v.w *= sc_w;
        ((float4*)&s_c[w][j * 128])[lane] = v;
    }
    __syncthreads();

    float* gout = g_pc + (size_t)(b * NCHUNK + chunk) * H_;
    for (int hh = tid; hh < H_; hh += 256) {
        float t = 0.f;
        #pragma unroll
        for (int wi = 0; wi < WARPS_B; ++wi) t += s_c[wi][hh];
        gout[hh] = t;
    }
}

// ---------------------------------------------------------------------------
// Kernel C1: combine chunk partials -> normalized context g_ctx[b][h]
// grid = B_, block = 512
__global__ __launch_bounds__(512) void combine_kernel()
{
    const int b = blockIdx.x;
    const int h = threadIdx.x;
    __shared__ float s_scale[NCHUNK];
    __shared__ float s_invl;

    if (h == 0) {
        float mg = g_pm[b * NCHUNK];
        #pragma unroll
        for (int c = 1; c < NCHUNK; ++c) mg = fmaxf(mg, g_pm[b * NCHUNK + c]);
        float lg = 0.f;
        #pragma unroll
        for (int c = 0; c < NCHUNK; ++c) {
            const float sc_ = __expf(g_pm[b * NCHUNK + c] - mg);
            s_scale[c] = sc_;
            lg = fmaf(sc_, g_pl[b * NCHUNK + c], lg);
        }
        s_invl = 1.0f / lg;
    }
    __syncthreads();

    float t = 0.f;
    #pragma unroll
    for (int c = 0; c < NCHUNK; ++c)
        t = fmaf(s_scale[c], g_pc[(size_t)(b * NCHUNK + c) * H_ + h], t);
    g_ctx[b * H_ + h] = t * s_invl;
}

// ---------------------------------------------------------------------------
// Kernel C2: out[b,a] = ctx[b] . WvT[a] + bv[a] — one WARP per output.
// grid = B_*A_/WARPS_B = 2048 blocks, block = 256. Fully coalesced.
__global__ __launch_bounds__(256) void out_kernel(
    const float* __restrict__ bv, float* __restrict__ out)
{
    const int gw   = blockIdx.x * WARPS_B + (threadIdx.x >> 5);
    const int lane = threadIdx.x & 31;
    const int b = gw >> 8;          // /256
    const int a = gw & (A_ - 1);    // %256

    const float* cr = g_ctx + b * H_;
    const float* wr = g_WvT + a * H_;
    float acc = 0.f;
    #pragma unroll
    for (int j = 0; j < H_ / 32; ++j) {
        const int h = j * 32 + lane;
        acc = fmaf(cr[h], wr[h], acc);
    }
    #pragma unroll
    for (int o = 16; o > 0; o >>= 1)
        acc += __shfl_xor_sync(0xffffffffu, acc, o);
    if (lane == 0) out[b * A_ + a] = acc + bv[a];
}

// ---------------------------------------------------------------------------
extern "C" void kernel_launch(void* const* d_in, const int* in_sizes, int n_in,
                              void* d_out, int out_size)
{
    const float* x    = (const float*)d_in[0];
    const float* hist = (const float*)d_in[1];
    const float* Wq   = (const float*)d_in[2];
    const float* bq   = (const float*)d_in[3];
    const float* Wk   = (const float*)d_in[4];
    const float* bk   = (const float*)d_in[5];
    const float* Wv   = (const float*)d_in[6];
    const float* bv   = (const float*)d_in[7];
    float* out = (float*)d_out;

    q_kernel<<<B_, 256>>>(x, Wq, bq, bk);
    qt_kernel<<<(B_ * H_) / WARPS_B, 256>>>(Wk);
    wvT_kernel<<<dim3(A_ / 32, H_ / 32), dim3(32, 8)>>>(Wv);
    attn_pass_kernel<<<dim3(NCHUNK, B_), 256>>>(hist);
    combine_kernel<<<B_, 512>>>();
    out_kernel<<<(B_ * A_) / WARPS_B, 256>>>(bv, out);
}